// round 6
// baseline (speedup 1.0000x reference)
#include <cuda_runtime.h>
#include <cuda_bf16.h>
#include <math.h>
#include <stdint.h>

// ---------------------------------------------------------------------------
// MLA forward. GEMMs: bf16x3 emulated fp32 on mma.sync m16n8k16 (HMMA).
// Operands stored as separate hi/lo bf16 planes in gmem; cp.async feeds
// 4 SMEM planes per stage (Ah/Al/Bh/Bl, XOR-swizzled); ldmatrix.x4 fragment
// loads; D = Ah*Bh + Ah*Bl + Al*Bh, fp32 accumulate.
// ---------------------------------------------------------------------------

#define BSZ    2
#define SEQ    2048
#define DMODEL 2048
#define NH     16
#define QLR    1536
#define KVLR   512
#define D_NOPE 128
#define D_ROPE 64
#define D_QK   192
#define D_V    128
#define MS     (BSZ*SEQ)          /* 4096 */
#define QDIM   (NH*D_QK)          /* 3072 */
#define KVD    (KVLR + D_ROPE)    /* 576  */
#define HDIM   (D_NOPE + D_V)     /* 256  */
#define EPSF   1e-6f

typedef __nv_bfloat16 bf16;

// ---------------- scratch: every tensor is [2][elems] bf16 planes ----------
__device__ bf16 g_xp   [2 * (size_t)MS * DMODEL];
__device__ bf16 g_wqaT [2 * (size_t)QLR * DMODEL];
__device__ bf16 g_wkvaT[2 * (size_t)KVD * DMODEL];
__device__ bf16 g_wqbT [2 * (size_t)QDIM * QLR];
__device__ bf16 g_wkvbP[2 * (size_t)KVLR * NH * HDIM];
__device__ bf16 g_wkvbT[2 * (size_t)NH * HDIM * KVLR];
__device__ bf16 g_woT  [2 * (size_t)DMODEL * DMODEL];
__device__ bf16 g_qa   [2 * (size_t)MS * QLR];
__device__ bf16 g_q    [2 * (size_t)MS * QDIM];
__device__ bf16 g_kv   [2 * (size_t)MS * KVD];
__device__ bf16 g_kext [2 * (size_t)MS * KVD];
__device__ bf16 g_kextT[2 * (size_t)BSZ * KVLR * SEQ];
__device__ bf16 g_qext [2 * (size_t)MS * NH * KVD];
__device__ float g_scores[(size_t)BSZ * NH * SEQ * SEQ];
__device__ bf16 g_attn [2 * (size_t)BSZ * NH * SEQ * SEQ];
__device__ bf16 g_olat [2 * (size_t)BSZ * NH * SEQ * KVLR];
__device__ bf16 g_ohead[2 * (size_t)MS * DMODEL];

// ------------------------------ helpers -------------------------------------
__device__ __forceinline__ void split2(float x, bf16& h, bf16& l) {
    h = __float2bfloat16_rn(x);
    l = __float2bfloat16_rn(x - __bfloat162float(h));
}
__device__ __forceinline__ float join2(bf16 h, bf16 l) {
    return __bfloat162float(h) + __bfloat162float(l);
}
__device__ __forceinline__ void cp16(uint32_t smem, const void* g, int srcBytes) {
    asm volatile("cp.async.cg.shared.global [%0], [%1], 16, %2;"
                 :: "r"(smem), "l"(g), "r"(srcBytes));
}
__device__ __forceinline__ void cp_commit() { asm volatile("cp.async.commit_group;"); }
__device__ __forceinline__ void cp_wait1()  { asm volatile("cp.async.wait_group 1;"); }

__device__ __forceinline__ void ldsm4(uint32_t* r, uint32_t addr) {
    asm volatile("ldmatrix.sync.aligned.m8n8.x4.shared.b16 {%0,%1,%2,%3}, [%4];"
                 : "=r"(r[0]), "=r"(r[1]), "=r"(r[2]), "=r"(r[3]) : "r"(addr));
}
__device__ __forceinline__ void mma_bf16(float* d, const uint32_t* a,
                                         uint32_t b0, uint32_t b1) {
    asm volatile(
        "mma.sync.aligned.m16n8k16.row.col.f32.bf16.bf16.f32 "
        "{%0,%1,%2,%3}, {%4,%5,%6,%7}, {%8,%9}, {%0,%1,%2,%3};"
        : "+f"(d[0]), "+f"(d[1]), "+f"(d[2]), "+f"(d[3])
        : "r"(a[0]), "r"(a[1]), "r"(a[2]), "r"(a[3]), "r"(b0), "r"(b1));
}

// ----------------------------- GEMM kernel ----------------------------------
// C = A * B^T. A: [M][K] planes (hi at A, lo at A+aPS), row stride lda.
// B: [N][K] planes, row stride ldb. CTA tile 128x128, K-slab 16, 8 warps,
// warp tile 64x32. outMode 0: fp32 C. outMode 1: bf16 planes C (lo at +cPS).
struct GemmP {
    const bf16 *A, *B; void* C;
    long long aPS, bPS, cPS;
    int M, N, K;
    long long lda, ldb, ldc;
    long long aSb, aSh, bSb, bSh, cSb, cSh;
    int nInner, causal, outMode;
};

// stage: Ah[0,4096) Al[4096,8192) Bh[8192,12288) Bl[12288,16384)
#define STG_BYTES 16384

__global__ __launch_bounds__(256, 2) void gemm_hmma(GemmP p) {
    __shared__ __align__(16) bf16 stg[3][4][128 * 16];   // 48KB

    const int m0 = blockIdx.y * 128;
    const int n0 = blockIdx.x * 128;
    if (p.causal == 1 && n0 >= m0 + 128) return;

    const int z  = blockIdx.z;
    const int zb = z / p.nInner;
    const int zh = z - zb * p.nInner;
    const bf16* A = p.A + zb * p.aSb + zh * p.aSh;
    const bf16* B = p.B + zb * p.bSb + zh * p.bSh;

    int kEnd = p.K;
    if (p.causal == 2) { int km = m0 + 128; if (km < kEnd) kEnd = km; }
    const int nSlab = kEnd >> 4;

    const int tid  = threadIdx.x;
    const int lane = tid & 31;
    const int warp = tid >> 5;
    const int wm   = warp >> 2;    // 0..1
    const int wn   = warp & 3;     // 0..3

    const uint32_t smBase = (uint32_t)__cvta_generic_to_shared(&stg[0][0][0]);

    // ---- producer addressing: thread -> row r, one 16B chunk c ----
    const int r  = tid >> 1;
    const int cc = tid & 1;
    const uint32_t pOff = (uint32_t)(r * 32 + ((cc ^ ((r >> 2) & 1)) << 4));

    const bf16* gA0 = A + (size_t)(m0 + r) * p.lda + cc * 8;
    const bf16* gA1 = gA0 + p.aPS;
    int nr = n0 + r;
    const bool bok = nr < p.N;
    if (!bok) nr = n0;
    const bf16* gB0 = B + (size_t)nr * p.ldb + cc * 8;
    const bf16* gB1 = gB0 + p.bPS;
    const int bsz = bok ? 16 : 0;

#define ISSUE(S)                                                               \
    do {                                                                       \
        uint32_t sb = smBase + (uint32_t)(((S) % 3) * STG_BYTES);              \
        const size_t ko = (size_t)(S) * 16;                                    \
        cp16(sb + pOff,         gA0 + ko, 16);                                 \
        cp16(sb + 4096 + pOff,  gA1 + ko, 16);                                 \
        cp16(sb + 8192 + pOff,  gB0 + ko, bsz);                                \
        cp16(sb + 12288 + pOff, gB1 + ko, bsz);                                \
    } while (0)

    // ---- consumer (ldmatrix) base offsets, plane-relative ----
    // A x4: mats (m0-7,kLo),(m8-15,kLo),(m0-7,kHi),(m8-15,kHi)
    const int rowA = wm * 64 + (lane & 7) + ((lane >> 3) & 1) * 8;
    const int cA   = lane >> 4;
    const uint32_t offA = (uint32_t)(rowA * 32 + ((cA ^ ((rowA >> 2) & 1)) << 4));
    // B x4: mats (nLo,kLo),(nLo,kHi),(nHi,kLo),(nHi,kHi)
    const int rowB = wn * 32 + (lane & 7) + ((lane >> 4) << 3);
    const int cB   = (lane >> 3) & 1;
    const uint32_t offB = (uint32_t)(rowB * 32 + ((cB ^ ((rowB >> 2) & 1)) << 4));

    float acc[4][4][4];
#pragma unroll
    for (int i = 0; i < 4; ++i)
#pragma unroll
        for (int j = 0; j < 4; ++j)
#pragma unroll
            for (int l = 0; l < 4; ++l) acc[i][j][l] = 0.f;

    // prologue: 2 slabs ahead
    ISSUE(0); cp_commit();
    if (nSlab > 1) ISSUE(1);
    cp_commit();

    for (int it = 0; it < nSlab; ++it) {
        cp_wait1();
        __syncthreads();

        const uint32_t sb   = smBase + (uint32_t)((it % 3) * STG_BYTES);
        const uint32_t aAdr = sb + offA;
        const uint32_t bAdr = sb + 8192 + offB;

        uint32_t bh[2][4], bl[2][4];
        ldsm4(bh[0], bAdr);
        ldsm4(bh[1], bAdr + 512);
        ldsm4(bl[0], bAdr + 4096);
        ldsm4(bl[1], bAdr + 4096 + 512);

#pragma unroll
        for (int mi = 0; mi < 4; ++mi) {
            uint32_t ah[4], al[4];
            ldsm4(ah, aAdr + mi * 512);
            ldsm4(al, aAdr + 4096 + mi * 512);
#pragma unroll
            for (int nt = 0; nt < 4; ++nt) {
                const int np = nt >> 1, hf = (nt & 1) * 2;
                const uint32_t b0h = bh[np][hf], b1h = bh[np][hf + 1];
                const uint32_t b0l = bl[np][hf], b1l = bl[np][hf + 1];
                mma_bf16(acc[mi][nt], ah, b0h, b1h);
                mma_bf16(acc[mi][nt], ah, b0l, b1l);
                mma_bf16(acc[mi][nt], al, b0h, b1h);
            }
        }

        __syncthreads();
        if (it + 2 < nSlab) ISSUE(it + 2);
        cp_commit();
    }
#undef ISSUE

    // ---- epilogue ----
    const int g = lane >> 2;
    const int c = lane & 3;
    if (p.outMode == 0) {
        float* C = (float*)p.C + zb * p.cSb + zh * p.cSh;
#pragma unroll
        for (int mi = 0; mi < 4; ++mi) {
            const int gm = m0 + wm * 64 + mi * 16 + g;
            float* r0 = C + (long long)gm * p.ldc;
            float* r1 = r0 + 8 * p.ldc;
#pragma unroll
            for (int nt = 0; nt < 4; ++nt) {
                const int gn = n0 + wn * 32 + nt * 8 + 2 * c;
                if (gn < p.N) {
                    *(float2*)(r0 + gn) = make_float2(acc[mi][nt][0], acc[mi][nt][1]);
                    *(float2*)(r1 + gn) = make_float2(acc[mi][nt][2], acc[mi][nt][3]);
                }
            }
        }
    } else {
        bf16* Ch = (bf16*)p.C + zb * p.cSb + zh * p.cSh;
        bf16* Cl = Ch + p.cPS;
#pragma unroll
        for (int mi = 0; mi < 4; ++mi) {
            const int gm = m0 + wm * 64 + mi * 16 + g;
            const long long ro0 = (long long)gm * p.ldc;
            const long long ro1 = ro0 + 8 * p.ldc;
#pragma unroll
            for (int nt = 0; nt < 4; ++nt) {
                const int gn = n0 + wn * 32 + nt * 8 + 2 * c;
                if (gn < p.N) {
                    bf16 h0, l0, h1, l1;
                    split2(acc[mi][nt][0], h0, l0);
                    split2(acc[mi][nt][1], h1, l1);
                    *(__nv_bfloat162*)(Ch + ro0 + gn) = __nv_bfloat162(h0, h1);
                    *(__nv_bfloat162*)(Cl + ro0 + gn) = __nv_bfloat162(l0, l1);
                    split2(acc[mi][nt][2], h0, l0);
                    split2(acc[mi][nt][3], h1, l1);
                    *(__nv_bfloat162*)(Ch + ro1 + gn) = __nv_bfloat162(h0, h1);
                    *(__nv_bfloat162*)(Cl + ro1 + gn) = __nv_bfloat162(l0, l1);
                }
            }
        }
    }
}

// ---------------------------- block reduction ------------------------------
__device__ __forceinline__ float blockReduce(float v, bool isMax) {
    __shared__ float sh[32];
    const int lane = threadIdx.x & 31, wid = threadIdx.x >> 5;
    __syncthreads();
#pragma unroll
    for (int o = 16; o > 0; o >>= 1) {
        float t = __shfl_down_sync(0xffffffffu, v, o);
        v = isMax ? fmaxf(v, t) : (v + t);
    }
    if (lane == 0) sh[wid] = v;
    __syncthreads();
    const int nw = blockDim.x >> 5;
    if (wid == 0) {
        v = (lane < nw) ? sh[lane] : (isMax ? -1e30f : 0.f);
#pragma unroll
        for (int o = 16; o > 0; o >>= 1) {
            float t = __shfl_down_sync(0xffffffffu, v, o);
            v = isMax ? fmaxf(v, t) : (v + t);
        }
        if (lane == 0) sh[0] = v;
    }
    __syncthreads();
    return sh[0];
}

// ------------------------------ aux kernels --------------------------------
__global__ void pack2_k(const float* __restrict__ in, bf16* __restrict__ out,
                        long long ps, int n) {
    for (int i = blockIdx.x * blockDim.x + threadIdx.x; i < n; i += gridDim.x * blockDim.x) {
        bf16 h, l; split2(in[i], h, l);
        out[i] = h; out[i + ps] = l;
    }
}

// fp32 [R][C] -> planes [C][R]
__global__ void packT2_k(const float* __restrict__ in, bf16* __restrict__ out,
                         long long ps, int R, int C) {
    __shared__ float t[32][33];
    const int c0 = blockIdx.x * 32, r0 = blockIdx.y * 32;
#pragma unroll
    for (int i = threadIdx.y; i < 32; i += 8)
        t[i][threadIdx.x] = in[(long long)(r0 + i) * C + c0 + threadIdx.x];
    __syncthreads();
#pragma unroll
    for (int i = threadIdx.y; i < 32; i += 8) {
        bf16 h, l; split2(t[threadIdx.x][i], h, l);
        long long o = (long long)(c0 + i) * R + r0 + threadIdx.x;
        out[o] = h; out[o + ps] = l;
    }
}

__global__ void rmsnorm_rows_k(bf16* x, long long ps, const float* __restrict__ w, int n) {
    long long base = (long long)blockIdx.x * n;
    float ss = 0.f;
    for (int i = threadIdx.x; i < n; i += blockDim.x) {
        float v = join2(x[base + i], x[base + i + ps]); ss += v * v;
    }
    ss = blockReduce(ss, false);
    float rn = rsqrtf(ss / (float)n + EPSF);
    for (int i = threadIdx.x; i < n; i += blockDim.x) {
        float v = join2(x[base + i], x[base + i + ps]) * rn * w[i];
        bf16 h, l; split2(v, h, l);
        x[base + i] = h; x[base + i + ps] = l;
    }
}

__global__ void kv_process_k(const bf16* __restrict__ kv, bf16* __restrict__ kext,
                             bf16* __restrict__ kextT,
                             const float* __restrict__ w, const float* __restrict__ freqs) {
    const long long psKV = (long long)MS * KVD;
    const long long psT  = (long long)BSZ * KVLR * SEQ;
    const int m = blockIdx.x;
    const int s = m & (SEQ - 1);
    const int b = m >> 11;
    const bf16* kr = kv   + (long long)m * KVD;
    bf16*       ke = kext + (long long)m * KVD;
    float ss = 0.f;
    for (int i = threadIdx.x; i < KVLR; i += blockDim.x) {
        float v = join2(kr[i], kr[i + psKV]); ss += v * v;
    }
    ss = blockReduce(ss, false);
    float rn = rsqrtf(ss / (float)KVLR + EPSF);
    for (int i = threadIdx.x; i < KVLR; i += blockDim.x) {
        float v = join2(kr[i], kr[i + psKV]) * rn * w[i];
        bf16 h, l; split2(v, h, l);
        ke[i] = h; ke[i + psKV] = l;
        long long o = (long long)b * KVLR * SEQ + (long long)i * SEQ + s;
        kextT[o] = h; kextT[o + psT] = l;
    }
    if (threadIdx.x < 32) {
        const int i = threadIdx.x;
        float th = freqs[s * 32 + i];
        float co, sn; sincosf(th, &sn, &co);
        float x0 = join2(kr[KVLR + 2 * i], kr[KVLR + 2 * i + psKV]);
        float x1 = join2(kr[KVLR + 2 * i + 1], kr[KVLR + 2 * i + 1 + psKV]);
        bf16 h, l;
        split2(x0 * co - x1 * sn, h, l);
        ke[KVLR + 2 * i] = h; ke[KVLR + 2 * i + psKV] = l;
        split2(x0 * sn + x1 * co, h, l);
        ke[KVLR + 2 * i + 1] = h; ke[KVLR + 2 * i + 1 + psKV] = l;
    }
}

__global__ void rope_q_k(const bf16* __restrict__ q, bf16* __restrict__ qext,
                         const float* __restrict__ freqs) {
    const long long psQ = (long long)MS * QDIM;
    const long long psE = (long long)MS * NH * KVD;
    const int m = blockIdx.x;
    const int s = m & (SEQ - 1);
    const int h = threadIdx.x >> 5;
    const int i = threadIdx.x & 31;
    float th = freqs[s * 32 + i];
    float co, sn; sincosf(th, &sn, &co);
    const bf16* qr = q + (long long)m * QDIM + h * D_QK + D_NOPE;
    bf16*       qe = qext + ((long long)m * NH + h) * KVD + KVLR;
    float x0 = join2(qr[2 * i], qr[2 * i + psQ]);
    float x1 = join2(qr[2 * i + 1], qr[2 * i + 1 + psQ]);
    bf16 hh, ll;
    split2(x0 * co - x1 * sn, hh, ll);
    qe[2 * i] = hh; qe[2 * i + psE] = ll;
    split2(x0 * sn + x1 * co, hh, ll);
    qe[2 * i + 1] = hh; qe[2 * i + 1 + psE] = ll;
}

__global__ void softmax_causal_k(const float* __restrict__ scores,
                                 bf16* __restrict__ attn, float scale) {
    const long long psA = (long long)BSZ * NH * SEQ * SEQ;
    const int s = blockIdx.x;
    long long base = ((long long)blockIdx.y * SEQ + s) * SEQ;
    const float* r = scores + base;
    bf16* ah = attn + base;
    bf16* al = ah + psA;
    const int n = s + 1;
    float mx = -1e30f;
    for (int t = threadIdx.x; t < n; t += blockDim.x) mx = fmaxf(mx, r[t]);
    mx = blockReduce(mx, true);
    float sum = 0.f;
    for (int t = threadIdx.x; t < n; t += blockDim.x)
        sum += __expf((r[t] - mx) * scale);
    sum = blockReduce(sum, false);
    float inv = 1.f / sum;
    for (int t = threadIdx.x; t < n; t += blockDim.x) {
        float e = __expf((r[t] - mx) * scale) * inv;
        bf16 h, l; split2(e, h, l);
        ah[t] = h; al[t] = l;
    }
    const bf16 z = __float2bfloat16_rn(0.f);
    const int bound = ((s >> 7) + 1) << 7;
    for (int t = n + threadIdx.x; t < bound; t += blockDim.x) { ah[t] = z; al[t] = z; }
}

// ------------------------------- host side ---------------------------------
static void launchGemm(const bf16* A, long long aPS, const bf16* B, long long bPS,
                       void* C, long long cPS,
                       int M, int N, int K,
                       long long lda, long long ldb, long long ldc,
                       int nb, int nInner,
                       long long aSb, long long aSh,
                       long long bSb, long long bSh,
                       long long cSb, long long cSh,
                       int causal, int outMode) {
    GemmP p;
    p.A = A; p.B = B; p.C = C;
    p.aPS = aPS; p.bPS = bPS; p.cPS = cPS;
    p.M = M; p.N = N; p.K = K;
    p.lda = lda; p.ldb = ldb; p.ldc = ldc;
    p.aSb = aSb; p.aSh = aSh; p.bSb = bSb; p.bSh = bSh; p.cSb = cSb; p.cSh = cSh;
    p.nInner = nInner; p.causal = causal; p.outMode = outMode;
    dim3 grid((N + 127) / 128, (M + 127) / 128, nb);
    gemm_hmma<<<grid, 256>>>(p);
}

extern "C" void kernel_launch(void* const* d_in, const int* in_sizes, int n_in,
                              void* d_out, int out_size) {
    const float* x         = (const float*)d_in[0];
    const float* freqs     = (const float*)d_in[1];
    const float* wq_a      = (const float*)d_in[3];
    const float* q_norm_w  = (const float*)d_in[4];
    const float* wq_b      = (const float*)d_in[5];
    const float* wkv_a     = (const float*)d_in[6];
    const float* kv_norm_w = (const float*)d_in[7];
    const float* wkv_b     = (const float*)d_in[8];
    const float* wo        = (const float*)d_in[9];
    float* out = (float*)d_out;

    bf16 *xp, *wqaT, *wkvaT, *wqbT, *wkvbP, *wkvbT, *woT;
    bf16 *qa, *q, *kv, *kext, *kextT, *qext, *attn, *olat, *ohead;
    float* scores;
    cudaGetSymbolAddress((void**)&xp,     g_xp);
    cudaGetSymbolAddress((void**)&wqaT,   g_wqaT);
    cudaGetSymbolAddress((void**)&wkvaT,  g_wkvaT);
    cudaGetSymbolAddress((void**)&wqbT,   g_wqbT);
    cudaGetSymbolAddress((void**)&wkvbP,  g_wkvbP);
    cudaGetSymbolAddress((void**)&wkvbT,  g_wkvbT);
    cudaGetSymbolAddress((void**)&woT,    g_woT);
    cudaGetSymbolAddress((void**)&qa,     g_qa);
    cudaGetSymbolAddress((void**)&q,      g_q);
    cudaGetSymbolAddress((void**)&kv,     g_kv);
    cudaGetSymbolAddress((void**)&kext,   g_kext);
    cudaGetSymbolAddress((void**)&kextT,  g_kextT);
    cudaGetSymbolAddress((void**)&qext,   g_qext);
    cudaGetSymbolAddress((void**)&scores, g_scores);
    cudaGetSymbolAddress((void**)&attn,   g_attn);
    cudaGetSymbolAddress((void**)&olat,   g_olat);
    cudaGetSymbolAddress((void**)&ohead,  g_ohead);

    const float scale = 1.0f / sqrtf((float)D_QK);

    // plane strides
    const long long psX   = (long long)MS * DMODEL;
    const long long psWQA = (long long)QLR * DMODEL;
    const long long psWKA = (long long)KVD * DMODEL;
    const long long psWQB = (long long)QDIM * QLR;
    const long long psWBP = (long long)KVLR * NH * HDIM;
    const long long psWBT = (long long)NH * HDIM * KVLR;
    const long long psWO  = (long long)DMODEL * DMODEL;
    const long long psQA  = (long long)MS * QLR;
    const long long psQ   = (long long)MS * QDIM;
    const long long psKV  = (long long)MS * KVD;
    const long long psKT  = (long long)BSZ * KVLR * SEQ;
    const long long psQE  = (long long)MS * NH * KVD;
    const long long psAT  = (long long)BSZ * NH * SEQ * SEQ;
    const long long psOL  = (long long)BSZ * NH * SEQ * KVLR;
    const long long psOH  = (long long)MS * DMODEL;

    // ---- pack inputs into planes ----
    pack2_k<<<512, 256>>>(x, xp, psX, MS * DMODEL);
    pack2_k<<<256, 256>>>(wkv_b, wkvbP, psWBP, KVLR * NH * HDIM);
    packT2_k<<<dim3(QLR / 32, DMODEL / 32), dim3(32, 8)>>>(wq_a, wqaT, psWQA, DMODEL, QLR);
    packT2_k<<<dim3(KVD / 32, DMODEL / 32), dim3(32, 8)>>>(wkv_a, wkvaT, psWKA, DMODEL, KVD);
    packT2_k<<<dim3(QDIM / 32, QLR / 32), dim3(32, 8)>>>(wq_b, wqbT, psWQB, QLR, QDIM);
    packT2_k<<<dim3((NH * HDIM) / 32, KVLR / 32), dim3(32, 8)>>>(wkv_b, wkvbT, psWBT, KVLR, NH * HDIM);
    packT2_k<<<dim3(DMODEL / 32, DMODEL / 32), dim3(32, 8)>>>(wo, woT, psWO, DMODEL, DMODEL);

    // 1. qa = x @ wq_a
    launchGemm(xp, psX, wqaT, psWQA, qa, psQA, MS, QLR, DMODEL,
               DMODEL, DMODEL, QLR, 1, 1, 0, 0, 0, 0, 0, 0, 0, 1);
    // 2. kv = x @ wkv_a (N=576)
    launchGemm(xp, psX, wkvaT, psWKA, kv, psKV, MS, KVD, DMODEL,
               DMODEL, DMODEL, KVD, 1, 1, 0, 0, 0, 0, 0, 0, 0, 1);
    // 3. rmsnorm(qa)
    rmsnorm_rows_k<<<MS, 256>>>(qa, psQA, q_norm_w, QLR);
    // 4. kext (+kextT)
    kv_process_k<<<MS, 256>>>(kv, kext, kextT, kv_norm_w, freqs);
    // 5. q = qa @ wq_b
    launchGemm(qa, psQA, wqbT, psWQB, q, psQ, MS, QDIM, QLR,
               QLR, QLR, QDIM, 1, 1, 0, 0, 0, 0, 0, 0, 0, 1);
    // 6. rope q_pe -> qext[:,512:576]
    rope_q_k<<<MS, NH * 32>>>(q, qext, freqs);
    // 7. qext[:,0:512] = q_nope @ wkv_b_nope^T
    launchGemm(q, psQ, wkvbP, psWBP, qext, psQE, MS, KVLR, D_NOPE,
               QDIM, NH * HDIM, (long long)NH * KVD,
               NH, NH, 0, D_QK, 0, HDIM, 0, KVD, 0, 1);
    // 8. scores = qext @ kext^T (fp32, causal tile skip)
    launchGemm(qext, psQE, kext, psKV, scores, 0, SEQ, SEQ, KVD,
               (long long)NH * KVD, KVD, SEQ,
               BSZ * NH, NH,
               (long long)SEQ * NH * KVD, KVD,
               (long long)SEQ * KVD, 0,
               (long long)NH * SEQ * SEQ, (long long)SEQ * SEQ,
               1, 0);
    // 9. softmax -> attn planes
    softmax_causal_k<<<dim3(SEQ, BSZ * NH), 256>>>(scores, attn, scale);
    // 10. olat = attn @ kv_cache (causal K-limit)
    launchGemm(attn, psAT, kextT, psKT, olat, psOL, SEQ, KVLR, SEQ,
               SEQ, SEQ, KVLR,
               BSZ * NH, NH,
               (long long)NH * SEQ * SEQ, (long long)SEQ * SEQ,
               (long long)KVLR * SEQ, 0,
               (long long)NH * SEQ * KVLR, (long long)SEQ * KVLR,
               2, 1);
    // 11. ohead = olat @ wkv_b_v^T
    launchGemm(olat, psOL, wkvbT + (long long)D_NOPE * KVLR, psWBT, ohead, psOH,
               SEQ, D_V, KVLR,
               KVLR, KVLR, DMODEL,
               BSZ * NH, NH,
               (long long)NH * SEQ * KVLR, (long long)SEQ * KVLR,
               0, (long long)HDIM * KVLR,
               (long long)SEQ * DMODEL, D_V,
               0, 1);
    // 12. out = ohead @ wo (fp32)
    launchGemm(ohead, psOH, woT, psWO, out, 0, MS, DMODEL, DMODEL,
               DMODEL, DMODEL, DMODEL, 1, 1, 0, 0, 0, 0, 0, 0, 0, 0);
}

// round 7
// speedup vs baseline: 1.3816x; 1.3816x over previous
#include <cuda_runtime.h>
#include <cuda_bf16.h>
#include <math.h>
#include <stdint.h>

// ---------------------------------------------------------------------------
// MLA forward, per-head expanded attention (k_abs / v materialized per head)
// to minimize MMA work on the legacy-HMMA-bound sm_103 tensor pipe.
// All GEMMs: bf16x3 emulated fp32 (hi/lo bf16 planes), mma.sync m16n8k16,
// cp.async 3-stage pipeline, ldmatrix fragment loads.
// ---------------------------------------------------------------------------

#define BSZ    2
#define SEQ    2048
#define DMODEL 2048
#define NH     16
#define QLR    1536
#define KVLR   512
#define D_NOPE 128
#define D_ROPE 64
#define D_QK   192
#define D_V    128
#define MS     (BSZ*SEQ)          /* 4096 */
#define QDIM   (NH*D_QK)          /* 3072 */
#define KVD    (KVLR + D_ROPE)    /* 576  */
#define HDIM   (D_NOPE + D_V)     /* 256  */
#define EPSF   1e-6f

typedef __nv_bfloat16 bf16;

// ---------------- scratch: every tensor is [2][elems] bf16 planes ----------
__device__ bf16 g_xp   [2 * (size_t)MS * DMODEL];
__device__ bf16 g_wqaT [2 * (size_t)QLR * DMODEL];
__device__ bf16 g_wkvaT[2 * (size_t)KVD * DMODEL];
__device__ bf16 g_wqbT [2 * (size_t)QDIM * QLR];
__device__ bf16 g_wkvbT[2 * (size_t)NH * HDIM * KVLR];
__device__ bf16 g_woT  [2 * (size_t)DMODEL * DMODEL];
__device__ bf16 g_qa   [2 * (size_t)MS * QLR];
__device__ bf16 g_q    [2 * (size_t)MS * QDIM];
__device__ bf16 g_kv   [2 * (size_t)MS * KVD];
__device__ bf16 g_kext [2 * (size_t)MS * KVD];
__device__ bf16 g_kfull[2 * (size_t)BSZ * NH * SEQ * D_QK];
__device__ bf16 g_vT   [2 * (size_t)BSZ * NH * D_V * SEQ];
__device__ float g_scores[(size_t)BSZ * NH * SEQ * SEQ];
__device__ bf16 g_attn [2 * (size_t)BSZ * NH * SEQ * SEQ];
__device__ bf16 g_ohead[2 * (size_t)MS * DMODEL];

// ------------------------------ helpers -------------------------------------
__device__ __forceinline__ void split2(float x, bf16& h, bf16& l) {
    h = __float2bfloat16_rn(x);
    l = __float2bfloat16_rn(x - __bfloat162float(h));
}
__device__ __forceinline__ float join2(bf16 h, bf16 l) {
    return __bfloat162float(h) + __bfloat162float(l);
}
__device__ __forceinline__ void cp16(uint32_t smem, const void* g, int srcBytes) {
    asm volatile("cp.async.cg.shared.global [%0], [%1], 16, %2;"
                 :: "r"(smem), "l"(g), "r"(srcBytes));
}
__device__ __forceinline__ void cp_commit() { asm volatile("cp.async.commit_group;"); }
__device__ __forceinline__ void cp_wait1()  { asm volatile("cp.async.wait_group 1;"); }

__device__ __forceinline__ void ldsm4(uint32_t* r, uint32_t addr) {
    asm volatile("ldmatrix.sync.aligned.m8n8.x4.shared.b16 {%0,%1,%2,%3}, [%4];"
                 : "=r"(r[0]), "=r"(r[1]), "=r"(r[2]), "=r"(r[3]) : "r"(addr));
}
__device__ __forceinline__ void mma_bf16(float* d, const uint32_t* a,
                                         uint32_t b0, uint32_t b1) {
    asm volatile(
        "mma.sync.aligned.m16n8k16.row.col.f32.bf16.bf16.f32 "
        "{%0,%1,%2,%3}, {%4,%5,%6,%7}, {%8,%9}, {%0,%1,%2,%3};"
        : "+f"(d[0]), "+f"(d[1]), "+f"(d[2]), "+f"(d[3])
        : "r"(a[0]), "r"(a[1]), "r"(a[2]), "r"(a[3]), "r"(b0), "r"(b1));
}

// ----------------------------- GEMM kernel ----------------------------------
// C = A * B^T. A: [M][K] planes (hi at A, lo at A+aPS), row stride lda.
// B: [N][K] planes, row stride ldb. CTA tile 128x128, K-slab 16, 8 warps,
// warp tile 64x32. outMode 0: fp32 C. outMode 1: bf16 planes C (lo at +cPS).
struct GemmP {
    const bf16 *A, *B; void* C;
    long long aPS, bPS, cPS;
    int M, N, K;
    long long lda, ldb, ldc;
    long long aSb, aSh, bSb, bSh, cSb, cSh;
    int nInner, causal, outMode;
};

// stage: Ah[0,4096) Al[4096,8192) Bh[8192,12288) Bl[12288,16384)
#define STG_BYTES 16384

__global__ __launch_bounds__(256, 2) void gemm_hmma(GemmP p) {
    __shared__ __align__(16) bf16 stg[3][4][128 * 16];   // 48KB

    const int m0 = blockIdx.y * 128;
    const int n0 = blockIdx.x * 128;
    if (p.causal == 1 && n0 >= m0 + 128) return;

    const int z  = blockIdx.z;
    const int zb = z / p.nInner;
    const int zh = z - zb * p.nInner;
    const bf16* A = p.A + zb * p.aSb + zh * p.aSh;
    const bf16* B = p.B + zb * p.bSb + zh * p.bSh;

    int kEnd = p.K;
    if (p.causal == 2) { int km = m0 + 128; if (km < kEnd) kEnd = km; }
    const int nSlab = kEnd >> 4;

    const int tid  = threadIdx.x;
    const int lane = tid & 31;
    const int warp = tid >> 5;
    const int wm   = warp >> 2;    // 0..1
    const int wn   = warp & 3;     // 0..3

    const uint32_t smBase = (uint32_t)__cvta_generic_to_shared(&stg[0][0][0]);

    // ---- producer addressing: thread -> row r, one 16B chunk cc ----
    const int r  = tid >> 1;
    const int cc = tid & 1;
    const uint32_t pOff = (uint32_t)(r * 32 + ((cc ^ ((r >> 2) & 1)) << 4));

    int mr = m0 + r;
    const bool aok = mr < p.M;
    if (!aok) mr = m0;
    const bf16* gA0 = A + (size_t)mr * p.lda + cc * 8;
    const bf16* gA1 = gA0 + p.aPS;
    const int asz = aok ? 16 : 0;
    int nr = n0 + r;
    const bool bok = nr < p.N;
    if (!bok) nr = n0;
    const bf16* gB0 = B + (size_t)nr * p.ldb + cc * 8;
    const bf16* gB1 = gB0 + p.bPS;
    const int bsz = bok ? 16 : 0;

#define ISSUE(S)                                                               \
    do {                                                                       \
        uint32_t sb = smBase + (uint32_t)(((S) % 3) * STG_BYTES);              \
        const size_t ko = (size_t)(S) * 16;                                    \
        cp16(sb + pOff,         gA0 + ko, asz);                                \
        cp16(sb + 4096 + pOff,  gA1 + ko, asz);                                \
        cp16(sb + 8192 + pOff,  gB0 + ko, bsz);                                \
        cp16(sb + 12288 + pOff, gB1 + ko, bsz);                                \
    } while (0)

    // ---- consumer (ldmatrix) base offsets, plane-relative ----
    const int rowA = wm * 64 + (lane & 7) + ((lane >> 3) & 1) * 8;
    const int cA   = lane >> 4;
    const uint32_t offA = (uint32_t)(rowA * 32 + ((cA ^ ((rowA >> 2) & 1)) << 4));
    const int rowB = wn * 32 + (lane & 7) + ((lane >> 4) << 3);
    const int cB   = (lane >> 3) & 1;
    const uint32_t offB = (uint32_t)(rowB * 32 + ((cB ^ ((rowB >> 2) & 1)) << 4));

    float acc[4][4][4];
#pragma unroll
    for (int i = 0; i < 4; ++i)
#pragma unroll
        for (int j = 0; j < 4; ++j)
#pragma unroll
            for (int l = 0; l < 4; ++l) acc[i][j][l] = 0.f;

    // prologue: 2 slabs ahead
    ISSUE(0); cp_commit();
    if (nSlab > 1) ISSUE(1);
    cp_commit();

    for (int it = 0; it < nSlab; ++it) {
        cp_wait1();
        __syncthreads();

        const uint32_t sb   = smBase + (uint32_t)((it % 3) * STG_BYTES);
        const uint32_t aAdr = sb + offA;
        const uint32_t bAdr = sb + 8192 + offB;

        uint32_t bh[2][4], bl[2][4];
        ldsm4(bh[0], bAdr);
        ldsm4(bh[1], bAdr + 512);
        ldsm4(bl[0], bAdr + 4096);
        ldsm4(bl[1], bAdr + 4096 + 512);

#pragma unroll
        for (int mi = 0; mi < 4; ++mi) {
            uint32_t ah[4], al[4];
            ldsm4(ah, aAdr + mi * 512);
            ldsm4(al, aAdr + 4096 + mi * 512);
#pragma unroll
            for (int nt = 0; nt < 4; ++nt) {
                const int np = nt >> 1, hf = (nt & 1) * 2;
                const uint32_t b0h = bh[np][hf], b1h = bh[np][hf + 1];
                const uint32_t b0l = bl[np][hf], b1l = bl[np][hf + 1];
                mma_bf16(acc[mi][nt], ah, b0h, b1h);
                mma_bf16(acc[mi][nt], ah, b0l, b1l);
                mma_bf16(acc[mi][nt], al, b0h, b1h);
            }
        }

        __syncthreads();
        if (it + 2 < nSlab) ISSUE(it + 2);
        cp_commit();
    }
#undef ISSUE

    // ---- epilogue ----
    const int g = lane >> 2;
    const int c = lane & 3;
    if (p.outMode == 0) {
        float* C = (float*)p.C + zb * p.cSb + zh * p.cSh;
#pragma unroll
        for (int mi = 0; mi < 4; ++mi) {
            const int gm = m0 + wm * 64 + mi * 16 + g;
            if (gm >= p.M) continue;
            float* r0 = C + (long long)gm * p.ldc;
            float* r1 = r0 + 8 * p.ldc;
#pragma unroll
            for (int nt = 0; nt < 4; ++nt) {
                const int gn = n0 + wn * 32 + nt * 8 + 2 * c;
                if (gn < p.N) {
                    *(float2*)(r0 + gn) = make_float2(acc[mi][nt][0], acc[mi][nt][1]);
                    *(float2*)(r1 + gn) = make_float2(acc[mi][nt][2], acc[mi][nt][3]);
                }
            }
        }
    } else {
        bf16* Ch = (bf16*)p.C + zb * p.cSb + zh * p.cSh;
        bf16* Cl = Ch + p.cPS;
#pragma unroll
        for (int mi = 0; mi < 4; ++mi) {
            const int gm = m0 + wm * 64 + mi * 16 + g;
            if (gm >= p.M) continue;
            const long long ro0 = (long long)gm * p.ldc;
            const long long ro1 = ro0 + 8 * p.ldc;
#pragma unroll
            for (int nt = 0; nt < 4; ++nt) {
                const int gn = n0 + wn * 32 + nt * 8 + 2 * c;
                if (gn < p.N) {
                    bf16 h0, l0, h1, l1;
                    split2(acc[mi][nt][0], h0, l0);
                    split2(acc[mi][nt][1], h1, l1);
                    *(__nv_bfloat162*)(Ch + ro0 + gn) = __nv_bfloat162(h0, h1);
                    *(__nv_bfloat162*)(Cl + ro0 + gn) = __nv_bfloat162(l0, l1);
                    split2(acc[mi][nt][2], h0, l0);
                    split2(acc[mi][nt][3], h1, l1);
                    *(__nv_bfloat162*)(Ch + ro1 + gn) = __nv_bfloat162(h0, h1);
                    *(__nv_bfloat162*)(Cl + ro1 + gn) = __nv_bfloat162(l0, l1);
                }
            }
        }
    }
}

// ---------------------------- block reduction ------------------------------
__device__ __forceinline__ float blockReduce(float v, bool isMax) {
    __shared__ float sh[32];
    const int lane = threadIdx.x & 31, wid = threadIdx.x >> 5;
    __syncthreads();
#pragma unroll
    for (int o = 16; o > 0; o >>= 1) {
        float t = __shfl_down_sync(0xffffffffu, v, o);
        v = isMax ? fmaxf(v, t) : (v + t);
    }
    if (lane == 0) sh[wid] = v;
    __syncthreads();
    const int nw = blockDim.x >> 5;
    if (wid == 0) {
        v = (lane < nw) ? sh[lane] : (isMax ? -1e30f : 0.f);
#pragma unroll
        for (int o = 16; o > 0; o >>= 1) {
            float t = __shfl_down_sync(0xffffffffu, v, o);
            v = isMax ? fmaxf(v, t) : (v + t);
        }
        if (lane == 0) sh[0] = v;
    }
    __syncthreads();
    return sh[0];
}

// ------------------------------ aux kernels --------------------------------
__global__ void pack2_k(const float* __restrict__ in, bf16* __restrict__ out,
                        long long ps, int n) {
    for (int i = blockIdx.x * blockDim.x + threadIdx.x; i < n; i += gridDim.x * blockDim.x) {
        bf16 h, l; split2(in[i], h, l);
        out[i] = h; out[i + ps] = l;
    }
}

// fp32 [R][C] -> planes [C][R]
__global__ void packT2_k(const float* __restrict__ in, bf16* __restrict__ out,
                         long long ps, int R, int C) {
    __shared__ float t[32][33];
    const int c0 = blockIdx.x * 32, r0 = blockIdx.y * 32;
#pragma unroll
    for (int i = threadIdx.y; i < 32; i += 8)
        t[i][threadIdx.x] = in[(long long)(r0 + i) * C + c0 + threadIdx.x];
    __syncthreads();
#pragma unroll
    for (int i = threadIdx.y; i < 32; i += 8) {
        bf16 h, l; split2(t[threadIdx.x][i], h, l);
        long long o = (long long)(c0 + i) * R + r0 + threadIdx.x;
        out[o] = h; out[o + ps] = l;
    }
}

__global__ void rmsnorm_rows_k(bf16* x, long long ps, const float* __restrict__ w, int n) {
    long long base = (long long)blockIdx.x * n;
    float ss = 0.f;
    for (int i = threadIdx.x; i < n; i += blockDim.x) {
        float v = join2(x[base + i], x[base + i + ps]); ss += v * v;
    }
    ss = blockReduce(ss, false);
    float rn = rsqrtf(ss / (float)n + EPSF);
    for (int i = threadIdx.x; i < n; i += blockDim.x) {
        float v = join2(x[base + i], x[base + i + ps]) * rn * w[i];
        bf16 h, l; split2(v, h, l);
        x[base + i] = h; x[base + i + ps] = l;
    }
}

__global__ void kv_process_k(const bf16* __restrict__ kv, bf16* __restrict__ kext,
                             const float* __restrict__ w, const float* __restrict__ freqs) {
    const long long psKV = (long long)MS * KVD;
    const int m = blockIdx.x;
    const int s = m & (SEQ - 1);
    const bf16* kr = kv   + (long long)m * KVD;
    bf16*       ke = kext + (long long)m * KVD;
    float ss = 0.f;
    for (int i = threadIdx.x; i < KVLR; i += blockDim.x) {
        float v = join2(kr[i], kr[i + psKV]); ss += v * v;
    }
    ss = blockReduce(ss, false);
    float rn = rsqrtf(ss / (float)KVLR + EPSF);
    for (int i = threadIdx.x; i < KVLR; i += blockDim.x) {
        float v = join2(kr[i], kr[i + psKV]) * rn * w[i];
        bf16 h, l; split2(v, h, l);
        ke[i] = h; ke[i + psKV] = l;
    }
    if (threadIdx.x < 32) {
        const int i = threadIdx.x;
        float th = freqs[s * 32 + i];
        float co, sn; sincosf(th, &sn, &co);
        float x0 = join2(kr[KVLR + 2 * i], kr[KVLR + 2 * i + psKV]);
        float x1 = join2(kr[KVLR + 2 * i + 1], kr[KVLR + 2 * i + 1 + psKV]);
        bf16 h, l;
        split2(x0 * co - x1 * sn, h, l);
        ke[KVLR + 2 * i] = h; ke[KVLR + 2 * i + psKV] = l;
        split2(x0 * sn + x1 * co, h, l);
        ke[KVLR + 2 * i + 1] = h; ke[KVLR + 2 * i + 1 + psKV] = l;
    }
}

// rope q_pe in place inside g_q planes ([m][h*192+128 .. +191])
__global__ void rope_q_k(bf16* q, const float* __restrict__ freqs) {
    const long long psQ = (long long)MS * QDIM;
    const int m = blockIdx.x;
    const int s = m & (SEQ - 1);
    const int h = threadIdx.x >> 5;
    const int i = threadIdx.x & 31;
    float th = freqs[s * 32 + i];
    float co, sn; sincosf(th, &sn, &co);
    bf16* qr = q + (long long)m * QDIM + h * D_QK + D_NOPE;
    float x0 = join2(qr[2 * i], qr[2 * i + psQ]);
    float x1 = join2(qr[2 * i + 1], qr[2 * i + 1 + psQ]);
    bf16 hh, ll;
    split2(x0 * co - x1 * sn, hh, ll);
    qr[2 * i] = hh; qr[2 * i + psQ] = ll;
    split2(x0 * sn + x1 * co, hh, ll);
    qr[2 * i + 1] = hh; qr[2 * i + 1 + psQ] = ll;
}

// broadcast roped k_pe into kfull[b,h,s,128:192] for all heads
__global__ void pe_bcast_k(const bf16* __restrict__ kext, bf16* __restrict__ kfull) {
    const long long psKV = (long long)MS * KVD;
    const long long psKF = (long long)BSZ * NH * SEQ * D_QK;
    const int m = blockIdx.x;
    const int s = m & (SEQ - 1);
    const int b = m >> 11;
    const bf16* pe = kext + (long long)m * KVD + KVLR;
    for (int idx = threadIdx.x; idx < NH * D_ROPE; idx += blockDim.x) {
        const int h = idx >> 6, j = idx & 63;
        long long o = (((long long)b * NH + h) * SEQ + s) * D_QK + D_NOPE + j;
        kfull[o] = pe[j];
        kfull[o + psKF] = pe[j + psKV];
    }
}

__global__ void softmax_causal_k(const float* __restrict__ scores,
                                 bf16* __restrict__ attn, float scale) {
    const long long psA = (long long)BSZ * NH * SEQ * SEQ;
    const int s = blockIdx.x;
    long long base = ((long long)blockIdx.y * SEQ + s) * SEQ;
    const float* r = scores + base;
    bf16* ah = attn + base;
    bf16* al = ah + psA;
    const int n = s + 1;
    float mx = -1e30f;
    for (int t = threadIdx.x; t < n; t += blockDim.x) mx = fmaxf(mx, r[t]);
    mx = blockReduce(mx, true);
    float sum = 0.f;
    for (int t = threadIdx.x; t < n; t += blockDim.x)
        sum += __expf((r[t] - mx) * scale);
    sum = blockReduce(sum, false);
    float inv = 1.f / sum;
    for (int t = threadIdx.x; t < n; t += blockDim.x) {
        float e = __expf((r[t] - mx) * scale) * inv;
        bf16 h, l; split2(e, h, l);
        ah[t] = h; al[t] = l;
    }
    const bf16 z = __float2bfloat16_rn(0.f);
    const int bound = ((s >> 7) + 1) << 7;
    for (int t = n + threadIdx.x; t < bound; t += blockDim.x) { ah[t] = z; al[t] = z; }
}

// ------------------------------- host side ---------------------------------
static void launchGemm(const bf16* A, long long aPS, const bf16* B, long long bPS,
                       void* C, long long cPS,
                       int M, int N, int K,
                       long long lda, long long ldb, long long ldc,
                       int nb, int nInner,
                       long long aSb, long long aSh,
                       long long bSb, long long bSh,
                       long long cSb, long long cSh,
                       int causal, int outMode) {
    GemmP p;
    p.A = A; p.B = B; p.C = C;
    p.aPS = aPS; p.bPS = bPS; p.cPS = cPS;
    p.M = M; p.N = N; p.K = K;
    p.lda = lda; p.ldb = ldb; p.ldc = ldc;
    p.aSb = aSb; p.aSh = aSh; p.bSb = bSb; p.bSh = bSh; p.cSb = cSb; p.cSh = cSh;
    p.nInner = nInner; p.causal = causal; p.outMode = outMode;
    dim3 grid((N + 127) / 128, (M + 127) / 128, nb);
    gemm_hmma<<<grid, 256>>>(p);
}

extern "C" void kernel_launch(void* const* d_in, const int* in_sizes, int n_in,
                              void* d_out, int out_size) {
    const float* x         = (const float*)d_in[0];
    const float* freqs     = (const float*)d_in[1];
    const float* wq_a      = (const float*)d_in[3];
    const float* q_norm_w  = (const float*)d_in[4];
    const float* wq_b      = (const float*)d_in[5];
    const float* wkv_a     = (const float*)d_in[6];
    const float* kv_norm_w = (const float*)d_in[7];
    const float* wkv_b     = (const float*)d_in[8];
    const float* wo        = (const float*)d_in[9];
    float* out = (float*)d_out;

    bf16 *xp, *wqaT, *wkvaT, *wqbT, *wkvbT, *woT;
    bf16 *qa, *q, *kv, *kext, *kfull, *vT, *attn, *ohead;
    float* scores;
    cudaGetSymbolAddress((void**)&xp,     g_xp);
    cudaGetSymbolAddress((void**)&wqaT,   g_wqaT);
    cudaGetSymbolAddress((void**)&wkvaT,  g_wkvaT);
    cudaGetSymbolAddress((void**)&wqbT,   g_wqbT);
    cudaGetSymbolAddress((void**)&wkvbT,  g_wkvbT);
    cudaGetSymbolAddress((void**)&woT,    g_woT);
    cudaGetSymbolAddress((void**)&qa,     g_qa);
    cudaGetSymbolAddress((void**)&q,      g_q);
    cudaGetSymbolAddress((void**)&kv,     g_kv);
    cudaGetSymbolAddress((void**)&kext,   g_kext);
    cudaGetSymbolAddress((void**)&kfull,  g_kfull);
    cudaGetSymbolAddress((void**)&vT,     g_vT);
    cudaGetSymbolAddress((void**)&scores, g_scores);
    cudaGetSymbolAddress((void**)&attn,   g_attn);
    cudaGetSymbolAddress((void**)&ohead,  g_ohead);

    const float scale = 1.0f / sqrtf((float)D_QK);

    // plane strides
    const long long psX   = (long long)MS * DMODEL;
    const long long psWQA = (long long)QLR * DMODEL;
    const long long psWKA = (long long)KVD * DMODEL;
    const long long psWQB = (long long)QDIM * QLR;
    const long long psWBT = (long long)NH * HDIM * KVLR;
    const long long psWO  = (long long)DMODEL * DMODEL;
    const long long psQA  = (long long)MS * QLR;
    const long long psQ   = (long long)MS * QDIM;
    const long long psKV  = (long long)MS * KVD;
    const long long psKF  = (long long)BSZ * NH * SEQ * D_QK;
    const long long psVT  = (long long)BSZ * NH * D_V * SEQ;
    const long long psAT  = (long long)BSZ * NH * SEQ * SEQ;
    const long long psOH  = (long long)MS * DMODEL;

    // ---- pack inputs into planes ----
    pack2_k<<<512, 256>>>(x, xp, psX, MS * DMODEL);
    packT2_k<<<dim3(QLR / 32, DMODEL / 32), dim3(32, 8)>>>(wq_a, wqaT, psWQA, DMODEL, QLR);
    packT2_k<<<dim3(KVD / 32, DMODEL / 32), dim3(32, 8)>>>(wkv_a, wkvaT, psWKA, DMODEL, KVD);
    packT2_k<<<dim3(QDIM / 32, QLR / 32), dim3(32, 8)>>>(wq_b, wqbT, psWQB, QLR, QDIM);
    packT2_k<<<dim3((NH * HDIM) / 32, KVLR / 32), dim3(32, 8)>>>(wkv_b, wkvbT, psWBT, KVLR, NH * HDIM);
    packT2_k<<<dim3(DMODEL / 32, DMODEL / 32), dim3(32, 8)>>>(wo, woT, psWO, DMODEL, DMODEL);

    // 1. qa = x @ wq_a
    launchGemm(xp, psX, wqaT, psWQA, qa, psQA, MS, QLR, DMODEL,
               DMODEL, DMODEL, QLR, 1, 1, 0, 0, 0, 0, 0, 0, 0, 1);
    // 2. kv = x @ wkv_a (N=576)
    launchGemm(xp, psX, wkvaT, psWKA, kv, psKV, MS, KVD, DMODEL,
               DMODEL, DMODEL, KVD, 1, 1, 0, 0, 0, 0, 0, 0, 0, 1);
    // 3. rmsnorm(qa)
    rmsnorm_rows_k<<<MS, 256>>>(qa, psQA, q_norm_w, QLR);
    // 4. kext = [rmsnorm(latent), rope(k_pe)]
    kv_process_k<<<MS, 256>>>(kv, kext, kv_norm_w, freqs);
    // 5. q = qa @ wq_b
    launchGemm(qa, psQA, wqbT, psWQB, q, psQ, MS, QDIM, QLR,
               QLR, QLR, QDIM, 1, 1, 0, 0, 0, 0, 0, 0, 0, 1);
    // 6. rope q_pe in place
    rope_q_k<<<MS, NH * 32>>>(q, freqs);
    // 7. k_abs: kfull[b,h,s,0:128] = kv_cache @ Wuk[h]^T
    launchGemm(kext, psKV, wkvbT, psWBT, kfull, psKF,
               SEQ, D_NOPE, KVLR,
               KVD, KVLR, D_QK,
               BSZ * NH, NH,
               (long long)SEQ * KVD, 0,
               0, (long long)HDIM * KVLR,
               (long long)NH * SEQ * D_QK, (long long)SEQ * D_QK,
               0, 1);
    // 8. broadcast roped k_pe into kfull[...,128:192]
    pe_bcast_k<<<MS, 256>>>(kext, kfull);
    // 9. vT[b,h,d,t] = Wuv[h] @ kv_cache^T
    launchGemm(wkvbT + (long long)D_NOPE * KVLR, psWBT, kext, psKV, vT, psVT,
               D_V, SEQ, KVLR,
               KVLR, KVD, SEQ,
               BSZ * NH, NH,
               0, (long long)HDIM * KVLR,
               (long long)SEQ * KVD, 0,
               (long long)NH * D_V * SEQ, (long long)D_V * SEQ,
               0, 1);
    // 10. scores = q @ kfull^T (K=192, fp32, causal tile skip)
    launchGemm(q, psQ, kfull, psKF, scores, 0,
               SEQ, SEQ, D_QK,
               QDIM, D_QK, SEQ,
               BSZ * NH, NH,
               (long long)SEQ * QDIM, D_QK,
               (long long)NH * SEQ * D_QK, (long long)SEQ * D_QK,
               (long long)NH * SEQ * SEQ, (long long)SEQ * SEQ,
               1, 0);
    // 11. softmax -> attn planes
    softmax_causal_k<<<dim3(SEQ, BSZ * NH), 256>>>(scores, attn, scale);
    // 12. ohead[b,s,h*128:...] = attn @ vT^T (causal K-limit)
    launchGemm(attn, psAT, vT, psVT, ohead, psOH,
               SEQ, D_V, SEQ,
               SEQ, SEQ, DMODEL,
               BSZ * NH, NH,
               (long long)NH * SEQ * SEQ, (long long)SEQ * SEQ,
               (long long)NH * D_V * SEQ, (long long)D_V * SEQ,
               (long long)SEQ * DMODEL, D_V,
               2, 1);
    // 13. out = ohead @ wo (fp32)
    launchGemm(ohead, psOH, woT, psWO, out, 0, MS, DMODEL, DMODEL,
               DMODEL, DMODEL, DMODEL, 1, 1, 0, 0, 0, 0, 0, 0, 0, 0);
}

// round 8
// speedup vs baseline: 1.5718x; 1.1376x over previous
#include <cuda_runtime.h>
#include <cuda_bf16.h>
#include <math.h>
#include <stdint.h>

// ---------------------------------------------------------------------------
// MLA forward, per-head expanded attention with FUSED flash-attention
// (scores -> online softmax -> attn*V in one kernel; no scores/attn buffers).
// All GEMMs: bf16x3 emulated fp32 (hi/lo bf16 planes), mma.sync m16n8k16,
// cp.async 3-stage pipeline, ldmatrix fragment loads.
// ---------------------------------------------------------------------------

#define BSZ    2
#define SEQ    2048
#define DMODEL 2048
#define NH     16
#define QLR    1536
#define KVLR   512
#define D_NOPE 128
#define D_ROPE 64
#define D_QK   192
#define D_V    128
#define MS     (BSZ*SEQ)          /* 4096 */
#define QDIM   (NH*D_QK)          /* 3072 */
#define KVD    (KVLR + D_ROPE)    /* 576  */
#define HDIM   (D_NOPE + D_V)     /* 256  */
#define EPSF   1e-6f

typedef __nv_bfloat16 bf16;

// ---------------- scratch: every tensor is [2][elems] bf16 planes ----------
__device__ bf16 g_xp   [2 * (size_t)MS * DMODEL];
__device__ bf16 g_wqaT [2 * (size_t)QLR * DMODEL];
__device__ bf16 g_wkvaT[2 * (size_t)KVD * DMODEL];
__device__ bf16 g_wqbT [2 * (size_t)QDIM * QLR];
__device__ bf16 g_wkvbT[2 * (size_t)NH * HDIM * KVLR];
__device__ bf16 g_woT  [2 * (size_t)DMODEL * DMODEL];
__device__ bf16 g_qa   [2 * (size_t)MS * QLR];
__device__ bf16 g_q    [2 * (size_t)MS * QDIM];
__device__ bf16 g_kv   [2 * (size_t)MS * KVD];
__device__ bf16 g_kext [2 * (size_t)MS * KVD];
__device__ bf16 g_kfull[2 * (size_t)BSZ * NH * SEQ * D_QK];
__device__ bf16 g_vT   [2 * (size_t)BSZ * NH * D_V * SEQ];
__device__ bf16 g_ohead[2 * (size_t)MS * DMODEL];

// ------------------------------ helpers -------------------------------------
__device__ __forceinline__ void split2(float x, bf16& h, bf16& l) {
    h = __float2bfloat16_rn(x);
    l = __float2bfloat16_rn(x - __bfloat162float(h));
}
__device__ __forceinline__ float join2(bf16 h, bf16 l) {
    return __bfloat162float(h) + __bfloat162float(l);
}
__device__ __forceinline__ void cp16(uint32_t smem, const void* g, int srcBytes) {
    asm volatile("cp.async.cg.shared.global [%0], [%1], 16, %2;"
                 :: "r"(smem), "l"(g), "r"(srcBytes));
}
__device__ __forceinline__ void cp_commit() { asm volatile("cp.async.commit_group;"); }
__device__ __forceinline__ void cp_wait1()  { asm volatile("cp.async.wait_group 1;"); }

__device__ __forceinline__ void ldsm4(uint32_t* r, uint32_t addr) {
    asm volatile("ldmatrix.sync.aligned.m8n8.x4.shared.b16 {%0,%1,%2,%3}, [%4];"
                 : "=r"(r[0]), "=r"(r[1]), "=r"(r[2]), "=r"(r[3]) : "r"(addr));
}
__device__ __forceinline__ void mma_bf16(float* d, const uint32_t* a,
                                         uint32_t b0, uint32_t b1) {
    asm volatile(
        "mma.sync.aligned.m16n8k16.row.col.f32.bf16.bf16.f32 "
        "{%0,%1,%2,%3}, {%4,%5,%6,%7}, {%8,%9}, {%0,%1,%2,%3};"
        : "+f"(d[0]), "+f"(d[1]), "+f"(d[2]), "+f"(d[3])
        : "r"(a[0]), "r"(a[1]), "r"(a[2]), "r"(a[3]), "r"(b0), "r"(b1));
}

// ----------------------------- GEMM kernel ----------------------------------
// C = A * B^T. A: [M][K] planes (hi at A, lo at A+aPS), row stride lda.
// B: [N][K] planes, row stride ldb. CTA tile 128x128, K-slab 16, 8 warps,
// warp tile 64x32. outMode 0: fp32 C. outMode 1: bf16 planes C (lo at +cPS).
struct GemmP {
    const bf16 *A, *B; void* C;
    long long aPS, bPS, cPS;
    int M, N, K;
    long long lda, ldb, ldc;
    long long aSb, aSh, bSb, bSh, cSb, cSh;
    int nInner, causal, outMode;
};

// stage: Ah[0,4096) Al[4096,8192) Bh[8192,12288) Bl[12288,16384)
#define STG_BYTES 16384

__global__ __launch_bounds__(256, 2) void gemm_hmma(GemmP p) {
    __shared__ __align__(16) bf16 stg[3][4][128 * 16];   // 48KB

    const int m0 = blockIdx.y * 128;
    const int n0 = blockIdx.x * 128;
    if (p.causal == 1 && n0 >= m0 + 128) return;

    const int z  = blockIdx.z;
    const int zb = z / p.nInner;
    const int zh = z - zb * p.nInner;
    const bf16* A = p.A + zb * p.aSb + zh * p.aSh;
    const bf16* B = p.B + zb * p.bSb + zh * p.bSh;

    int kEnd = p.K;
    if (p.causal == 2) { int km = m0 + 128; if (km < kEnd) kEnd = km; }
    const int nSlab = kEnd >> 4;

    const int tid  = threadIdx.x;
    const int lane = tid & 31;
    const int warp = tid >> 5;
    const int wm   = warp >> 2;    // 0..1
    const int wn   = warp & 3;     // 0..3

    const uint32_t smBase = (uint32_t)__cvta_generic_to_shared(&stg[0][0][0]);

    // ---- producer addressing: thread -> row r, one 16B chunk cc ----
    const int r  = tid >> 1;
    const int cc = tid & 1;
    const uint32_t pOff = (uint32_t)(r * 32 + ((cc ^ ((r >> 2) & 1)) << 4));

    int mr = m0 + r;
    const bool aok = mr < p.M;
    if (!aok) mr = m0;
    const bf16* gA0 = A + (size_t)mr * p.lda + cc * 8;
    const bf16* gA1 = gA0 + p.aPS;
    const int asz = aok ? 16 : 0;
    int nr = n0 + r;
    const bool bok = nr < p.N;
    if (!bok) nr = n0;
    const bf16* gB0 = B + (size_t)nr * p.ldb + cc * 8;
    const bf16* gB1 = gB0 + p.bPS;
    const int bsz = bok ? 16 : 0;

#define ISSUE(S)                                                               \
    do {                                                                       \
        uint32_t sb = smBase + (uint32_t)(((S) % 3) * STG_BYTES);              \
        const size_t ko = (size_t)(S) * 16;                                    \
        cp16(sb + pOff,         gA0 + ko, asz);                                \
        cp16(sb + 4096 + pOff,  gA1 + ko, asz);                                \
        cp16(sb + 8192 + pOff,  gB0 + ko, bsz);                                \
        cp16(sb + 12288 + pOff, gB1 + ko, bsz);                                \
    } while (0)

    // ---- consumer (ldmatrix) base offsets, plane-relative ----
    const int rowA = wm * 64 + (lane & 7) + ((lane >> 3) & 1) * 8;
    const int cA   = lane >> 4;
    const uint32_t offA = (uint32_t)(rowA * 32 + ((cA ^ ((rowA >> 2) & 1)) << 4));
    const int rowB = wn * 32 + (lane & 7) + ((lane >> 4) << 3);
    const int cB   = (lane >> 3) & 1;
    const uint32_t offB = (uint32_t)(rowB * 32 + ((cB ^ ((rowB >> 2) & 1)) << 4));

    float acc[4][4][4];
#pragma unroll
    for (int i = 0; i < 4; ++i)
#pragma unroll
        for (int j = 0; j < 4; ++j)
#pragma unroll
            for (int l = 0; l < 4; ++l) acc[i][j][l] = 0.f;

    // prologue: 2 slabs ahead
    ISSUE(0); cp_commit();
    if (nSlab > 1) ISSUE(1);
    cp_commit();

    for (int it = 0; it < nSlab; ++it) {
        cp_wait1();
        __syncthreads();   // stage (it)%3 ready; also orders prior-iter reads
                           // before this iter's ISSUE overwrite of (it-1)%3

        const uint32_t sb   = smBase + (uint32_t)((it % 3) * STG_BYTES);
        const uint32_t aAdr = sb + offA;
        const uint32_t bAdr = sb + 8192 + offB;

        uint32_t bh[2][4], bl[2][4];
        ldsm4(bh[0], bAdr);
        ldsm4(bh[1], bAdr + 512);
        ldsm4(bl[0], bAdr + 4096);
        ldsm4(bl[1], bAdr + 4096 + 512);

#pragma unroll
        for (int mi = 0; mi < 4; ++mi) {
            uint32_t ah[4], al[4];
            ldsm4(ah, aAdr + mi * 512);
            ldsm4(al, aAdr + 4096 + mi * 512);
#pragma unroll
            for (int nt = 0; nt < 4; ++nt) {
                const int np = nt >> 1, hf = (nt & 1) * 2;
                const uint32_t b0h = bh[np][hf], b1h = bh[np][hf + 1];
                const uint32_t b0l = bl[np][hf], b1l = bl[np][hf + 1];
                mma_bf16(acc[mi][nt], ah, b0h, b1h);
                mma_bf16(acc[mi][nt], ah, b0l, b1l);
                mma_bf16(acc[mi][nt], al, b0h, b1h);
            }
        }

        if (it + 2 < nSlab) ISSUE(it + 2);
        cp_commit();
    }
#undef ISSUE

    // ---- epilogue ----
    const int g = lane >> 2;
    const int c = lane & 3;
    if (p.outMode == 0) {
        float* C = (float*)p.C + zb * p.cSb + zh * p.cSh;
#pragma unroll
        for (int mi = 0; mi < 4; ++mi) {
            const int gm = m0 + wm * 64 + mi * 16 + g;
            if (gm >= p.M) continue;
            float* r0 = C + (long long)gm * p.ldc;
            float* r1 = r0 + 8 * p.ldc;
#pragma unroll
            for (int nt = 0; nt < 4; ++nt) {
                const int gn = n0 + wn * 32 + nt * 8 + 2 * c;
                if (gn < p.N) {
                    *(float2*)(r0 + gn) = make_float2(acc[mi][nt][0], acc[mi][nt][1]);
                    *(float2*)(r1 + gn) = make_float2(acc[mi][nt][2], acc[mi][nt][3]);
                }
            }
        }
    } else {
        bf16* Ch = (bf16*)p.C + zb * p.cSb + zh * p.cSh;
        bf16* Cl = Ch + p.cPS;
#pragma unroll
        for (int mi = 0; mi < 4; ++mi) {
            const int gm = m0 + wm * 64 + mi * 16 + g;
            if (gm >= p.M) continue;
            const long long ro0 = (long long)gm * p.ldc;
            const long long ro1 = ro0 + 8 * p.ldc;
#pragma unroll
            for (int nt = 0; nt < 4; ++nt) {
                const int gn = n0 + wn * 32 + nt * 8 + 2 * c;
                if (gn < p.N) {
                    bf16 h0, l0, h1, l1;
                    split2(acc[mi][nt][0], h0, l0);
                    split2(acc[mi][nt][1], h1, l1);
                    *(__nv_bfloat162*)(Ch + ro0 + gn) = __nv_bfloat162(h0, h1);
                    *(__nv_bfloat162*)(Cl + ro0 + gn) = __nv_bfloat162(l0, l1);
                    split2(acc[mi][nt][2], h0, l0);
                    split2(acc[mi][nt][3], h1, l1);
                    *(__nv_bfloat162*)(Ch + ro1 + gn) = __nv_bfloat162(h0, h1);
                    *(__nv_bfloat162*)(Cl + ro1 + gn) = __nv_bfloat162(l0, l1);
                }
            }
        }
    }
}

// --------------------------- flash attention --------------------------------
// One CTA per (q-block 128, (b,h)). Q held in smem; K/V streamed via the
// 3-stage cp.async ring across phase boundaries. Online softmax in registers.
// smem layout (bytes):
//   Qh 0..51200   Ql 51200..102400          (128 rows x 400B, 192 cols used)
//   Ph 102400..137216  Pl 137216..172032    (128 rows x 272B, 128 cols used)
//   stages 172032 + s*8192 (Bh 4KB, Bl 4KB)
//   RED 196608..198656 (float[4][128])
#define FL_SMEM 198656

__global__ __launch_bounds__(256, 1) void flash_k(
    const bf16* __restrict__ q, const bf16* __restrict__ kfull,
    const bf16* __restrict__ vT, bf16* __restrict__ ohead, float s2) {
    extern __shared__ __align__(16) char dyn[];
    const int tid = threadIdx.x, lane = tid & 31, warp = tid >> 5;
    const int wm = warp >> 2, wn = warp & 3, g = lane >> 2, c = lane & 3;
    const int iq = 15 - blockIdx.x;       // heavy blocks first
    const int bh = blockIdx.y, b = bh >> 4, h = bh & 15;
    const int m0 = iq * 128;
    const long long psQ  = (long long)MS * QDIM;
    const long long psKF = (long long)BSZ * NH * SEQ * D_QK;
    const long long psVT = (long long)BSZ * NH * D_V * SEQ;
    const long long psOH = (long long)MS * DMODEL;

    const uint32_t smb = (uint32_t)__cvta_generic_to_shared(dyn);
    const uint32_t smQ = smb;
    const uint32_t smP = smb + 102400;
    const uint32_t smS = smb + 172032;
    float* RED = (float*)(dyn + 196608);

    // ---- Q block load (one commit group) ----
    {
        const int r = tid >> 1, hf = tid & 1;
        const bf16* src = q + ((size_t)(b * SEQ + m0 + r)) * QDIM + h * D_QK + hf * 96;
        const uint32_t d0 = smQ + (uint32_t)(r * 400 + hf * 192);
#pragma unroll
        for (int ch = 0; ch < 12; ++ch) {
            cp16(d0 + ch * 16, src + ch * 8, 16);
            cp16(d0 + 51200 + ch * 16, src + psQ + ch * 8, 16);
        }
        cp_commit();
    }

    const int prow = tid >> 1, pcc = tid & 1;
    const uint32_t pOff = (uint32_t)(prow * 32 + ((pcc ^ ((prow >> 2) & 1)) << 4));
    const bf16* kf = kfull + (size_t)bh * SEQ * D_QK;
    const bf16* vt = vT + (size_t)bh * D_V * SEQ;
    const int u_total = 20 * (iq + 1);

    // slab u -> (kv block j = u/20, s = u%20): s<12 K-slab (K=192), else V-slab
#define FL_ISSUE(U)                                                            \
    do {                                                                       \
        const int _j = (U) / 20, _s = (U) % 20;                                \
        uint32_t _sb = smS + (uint32_t)(((U) % 3) * 8192);                     \
        const bf16* _s0; long long _ps;                                        \
        if (_s < 12) {                                                         \
            _s0 = kf + ((size_t)(_j * 128 + prow)) * D_QK + _s * 16 + pcc * 8; \
            _ps = psKF;                                                        \
        } else {                                                               \
            _s0 = vt + (size_t)prow * SEQ + _j * 128 + (_s - 12) * 16 + pcc * 8; \
            _ps = psVT;                                                        \
        }                                                                      \
        cp16(_sb + pOff, _s0, 16);                                             \
        cp16(_sb + 4096 + pOff, _s0 + _ps, 16);                                \
    } while (0)

    FL_ISSUE(0); cp_commit();
    FL_ISSUE(1); cp_commit();

    // consumer fragment offsets
    const int rowA = wm * 64 + (lane & 7) + ((lane >> 3) & 1) * 8;
    const int cA   = lane >> 4;
    const uint32_t offAq = (uint32_t)(rowA * 400 + cA * 16);
    const uint32_t offAp = (uint32_t)(rowA * 272 + cA * 16);
    const int rowB = wn * 32 + (lane & 7) + ((lane >> 4) << 3);
    const int cB   = (lane >> 3) & 1;
    const uint32_t offB = (uint32_t)(rowB * 32 + ((cB ^ ((rowB >> 2) & 1)) << 4));

    float oacc[4][4][4];
    float m_r[4][2], l_r[4][2];
#pragma unroll
    for (int mi = 0; mi < 4; ++mi) {
#pragma unroll
        for (int nt = 0; nt < 4; ++nt)
#pragma unroll
            for (int k = 0; k < 4; ++k) oacc[mi][nt][k] = 0.f;
        m_r[mi][0] = m_r[mi][1] = -1e30f;
        l_r[mi][0] = l_r[mi][1] = 0.f;
    }

    int u = 0;
    for (int j = 0; j <= iq; ++j) {
        float sacc[4][4][4];
#pragma unroll
        for (int mi = 0; mi < 4; ++mi)
#pragma unroll
            for (int nt = 0; nt < 4; ++nt)
#pragma unroll
                for (int k = 0; k < 4; ++k) sacc[mi][nt][k] = 0.f;

        // ---- S phase: 12 K-slabs (K=192) ----
        for (int s = 0; s < 12; ++s) {
            cp_wait1(); __syncthreads();
            const uint32_t sb = smS + (uint32_t)((u % 3) * 8192);
            uint32_t bh4[2][4], bl4[2][4];
            ldsm4(bh4[0], sb + offB); ldsm4(bh4[1], sb + offB + 512);
            ldsm4(bl4[0], sb + 4096 + offB); ldsm4(bl4[1], sb + 4096 + offB + 512);
#pragma unroll
            for (int mi = 0; mi < 4; ++mi) {
                uint32_t ah[4], al[4];
                ldsm4(ah, smQ + offAq + mi * 6400 + s * 32);
                ldsm4(al, smQ + 51200 + offAq + mi * 6400 + s * 32);
#pragma unroll
                for (int nt = 0; nt < 4; ++nt) {
                    const int np = nt >> 1, hf2 = (nt & 1) * 2;
                    mma_bf16(sacc[mi][nt], ah, bh4[np][hf2], bh4[np][hf2 + 1]);
                    mma_bf16(sacc[mi][nt], ah, bl4[np][hf2], bl4[np][hf2 + 1]);
                    mma_bf16(sacc[mi][nt], al, bh4[np][hf2], bh4[np][hf2 + 1]);
                }
            }
            if (u + 2 < u_total) FL_ISSUE(u + 2);
            cp_commit(); ++u;
        }

        // ---- diagonal block mask ----
        if (j == iq) {
#pragma unroll
            for (int mi = 0; mi < 4; ++mi)
#pragma unroll
                for (int nt = 0; nt < 4; ++nt)
#pragma unroll
                    for (int k = 0; k < 4; ++k) {
                        const int rl = wm * 64 + mi * 16 + g + (k >> 1) * 8;
                        const int cl = wn * 32 + nt * 8 + 2 * c + (k & 1);
                        if (cl > rl) sacc[mi][nt][k] = -1e30f;
                    }
        }

        // ---- online softmax ----
        float alpha[4][2];
#pragma unroll
        for (int mi = 0; mi < 4; ++mi)
#pragma unroll
            for (int h2 = 0; h2 < 2; ++h2) {
                float v = fmaxf(fmaxf(sacc[mi][0][h2 * 2], sacc[mi][0][h2 * 2 + 1]),
                                fmaxf(sacc[mi][1][h2 * 2], sacc[mi][1][h2 * 2 + 1]));
                v = fmaxf(v, fmaxf(fmaxf(sacc[mi][2][h2 * 2], sacc[mi][2][h2 * 2 + 1]),
                                   fmaxf(sacc[mi][3][h2 * 2], sacc[mi][3][h2 * 2 + 1])));
                v = fmaxf(v, __shfl_xor_sync(0xffffffffu, v, 1));
                v = fmaxf(v, __shfl_xor_sync(0xffffffffu, v, 2));
                if (c == 0) RED[wn * 128 + wm * 64 + mi * 16 + g + h2 * 8] = v;
            }
        __syncthreads();
#pragma unroll
        for (int mi = 0; mi < 4; ++mi)
#pragma unroll
            for (int h2 = 0; h2 < 2; ++h2) {
                const int row = wm * 64 + mi * 16 + g + h2 * 8;
                float mrow = fmaxf(fmaxf(RED[row], RED[128 + row]),
                                   fmaxf(RED[256 + row], RED[384 + row]));
                float mnew = fmaxf(m_r[mi][h2], mrow);
                alpha[mi][h2] = exp2f((m_r[mi][h2] - mnew) * s2);
                m_r[mi][h2] = mnew;
            }
        __syncthreads();   // RED reads done before sum-round rewrite
#pragma unroll
        for (int mi = 0; mi < 4; ++mi)
#pragma unroll
            for (int h2 = 0; h2 < 2; ++h2) {
                const float mn = m_r[mi][h2];
                const float a = alpha[mi][h2];
                float sum = 0.f;
#pragma unroll
                for (int nt = 0; nt < 4; ++nt) {
                    float p0 = exp2f((sacc[mi][nt][h2 * 2] - mn) * s2);
                    float p1 = exp2f((sacc[mi][nt][h2 * 2 + 1] - mn) * s2);
                    sacc[mi][nt][h2 * 2] = p0;
                    sacc[mi][nt][h2 * 2 + 1] = p1;
                    oacc[mi][nt][h2 * 2] *= a;
                    oacc[mi][nt][h2 * 2 + 1] *= a;
                    sum += p0 + p1;
                }
                sum += __shfl_xor_sync(0xffffffffu, sum, 1);
                sum += __shfl_xor_sync(0xffffffffu, sum, 2);
                if (c == 0) RED[wn * 128 + wm * 64 + mi * 16 + g + h2 * 8] = sum;
            }
        // write P planes to smem
#pragma unroll
        for (int mi = 0; mi < 4; ++mi)
#pragma unroll
            for (int nt = 0; nt < 4; ++nt) {
                const int r0 = wm * 64 + mi * 16 + g;
                const int cb = wn * 32 + nt * 8 + 2 * c;
                bf16 h0, l0, h1, l1;
                split2(sacc[mi][nt][0], h0, l0); split2(sacc[mi][nt][1], h1, l1);
                *(__nv_bfloat162*)(dyn + 102400 + r0 * 272 + cb * 2) = __nv_bfloat162(h0, h1);
                *(__nv_bfloat162*)(dyn + 137216 + r0 * 272 + cb * 2) = __nv_bfloat162(l0, l1);
                split2(sacc[mi][nt][2], h0, l0); split2(sacc[mi][nt][3], h1, l1);
                *(__nv_bfloat162*)(dyn + 102400 + (r0 + 8) * 272 + cb * 2) = __nv_bfloat162(h0, h1);
                *(__nv_bfloat162*)(dyn + 137216 + (r0 + 8) * 272 + cb * 2) = __nv_bfloat162(l0, l1);
            }
        __syncthreads();   // P + sums visible
#pragma unroll
        for (int mi = 0; mi < 4; ++mi)
#pragma unroll
            for (int h2 = 0; h2 < 2; ++h2) {
                const int row = wm * 64 + mi * 16 + g + h2 * 8;
                const float ls = RED[row] + RED[128 + row] + RED[256 + row] + RED[384 + row];
                l_r[mi][h2] = l_r[mi][h2] * alpha[mi][h2] + ls;
            }

        // ---- PV phase: 8 V-slabs (K=128 over t) ----
        for (int s = 0; s < 8; ++s) {
            cp_wait1(); __syncthreads();
            const uint32_t sb = smS + (uint32_t)((u % 3) * 8192);
            uint32_t vh4[2][4], vl4[2][4];
            ldsm4(vh4[0], sb + offB); ldsm4(vh4[1], sb + offB + 512);
            ldsm4(vl4[0], sb + 4096 + offB); ldsm4(vl4[1], sb + 4096 + offB + 512);
#pragma unroll
            for (int mi = 0; mi < 4; ++mi) {
                uint32_t ph[4], pl[4];
                ldsm4(ph, smP + offAp + mi * 4352 + s * 32);
                ldsm4(pl, smP + 34816 + offAp + mi * 4352 + s * 32);
#pragma unroll
                for (int nt = 0; nt < 4; ++nt) {
                    const int np = nt >> 1, hf2 = (nt & 1) * 2;
                    mma_bf16(oacc[mi][nt], ph, vh4[np][hf2], vh4[np][hf2 + 1]);
                    mma_bf16(oacc[mi][nt], ph, vl4[np][hf2], vl4[np][hf2 + 1]);
                    mma_bf16(oacc[mi][nt], pl, vh4[np][hf2], vh4[np][hf2 + 1]);
                }
            }
            if (u + 2 < u_total) FL_ISSUE(u + 2);
            cp_commit(); ++u;
        }
    }
#undef FL_ISSUE

    // ---- epilogue: O / l -> ohead planes ----
    bf16* Cb = ohead + (size_t)(b * SEQ + m0) * DMODEL + h * D_V;
#pragma unroll
    for (int mi = 0; mi < 4; ++mi) {
        const int r0 = wm * 64 + mi * 16 + g;
        const float i0 = 1.f / l_r[mi][0], i1 = 1.f / l_r[mi][1];
#pragma unroll
        for (int nt = 0; nt < 4; ++nt) {
            const int cb = wn * 32 + nt * 8 + 2 * c;
            bf16 h0, l0, h1, l1;
            split2(oacc[mi][nt][0] * i0, h0, l0);
            split2(oacc[mi][nt][1] * i0, h1, l1);
            bf16* p = Cb + (size_t)r0 * DMODEL + cb;
            *(__nv_bfloat162*)p = __nv_bfloat162(h0, h1);
            *(__nv_bfloat162*)(p + psOH) = __nv_bfloat162(l0, l1);
            split2(oacc[mi][nt][2] * i1, h0, l0);
            split2(oacc[mi][nt][3] * i1, h1, l1);
            p = Cb + (size_t)(r0 + 8) * DMODEL + cb;
            *(__nv_bfloat162*)p = __nv_bfloat162(h0, h1);
            *(__nv_bfloat162*)(p + psOH) = __nv_bfloat162(l0, l1);
        }
    }
}

// ---------------------------- block reduction ------------------------------
__device__ __forceinline__ float blockReduce(float v, bool isMax) {
    __shared__ float sh[32];
    const int lane = threadIdx.x & 31, wid = threadIdx.x >> 5;
    __syncthreads();
#pragma unroll
    for (int o = 16; o > 0; o >>= 1) {
        float t = __shfl_down_sync(0xffffffffu, v, o);
        v = isMax ? fmaxf(v, t) : (v + t);
    }
    if (lane == 0) sh[wid] = v;
    __syncthreads();
    const int nw = blockDim.x >> 5;
    if (wid == 0) {
        v = (lane < nw) ? sh[lane] : (isMax ? -1e30f : 0.f);
#pragma unroll
        for (int o = 16; o > 0; o >>= 1) {
            float t = __shfl_down_sync(0xffffffffu, v, o);
            v = isMax ? fmaxf(v, t) : (v + t);
        }
        if (lane == 0) sh[0] = v;
    }
    __syncthreads();
    return sh[0];
}

// ------------------------------ aux kernels --------------------------------
__global__ void pack2_k(const float* __restrict__ in, bf16* __restrict__ out,
                        long long ps, int n) {
    for (int i = blockIdx.x * blockDim.x + threadIdx.x; i < n; i += gridDim.x * blockDim.x) {
        bf16 h, l; split2(in[i], h, l);
        out[i] = h; out[i + ps] = l;
    }
}

// fp32 [R][C] -> planes [C][R]
__global__ void packT2_k(const float* __restrict__ in, bf16* __restrict__ out,
                         long long ps, int R, int C) {
    __shared__ float t[32][33];
    const int c0 = blockIdx.x * 32, r0 = blockIdx.y * 32;
#pragma unroll
    for (int i = threadIdx.y; i < 32; i += 8)
        t[i][threadIdx.x] = in[(long long)(r0 + i) * C + c0 + threadIdx.x];
    __syncthreads();
#pragma unroll
    for (int i = threadIdx.y; i < 32; i += 8) {
        bf16 h, l; split2(t[threadIdx.x][i], h, l);
        long long o = (long long)(c0 + i) * R + r0 + threadIdx.x;
        out[o] = h; out[o + ps] = l;
    }
}

__global__ void rmsnorm_rows_k(bf16* x, long long ps, const float* __restrict__ w, int n) {
    long long base = (long long)blockIdx.x * n;
    float ss = 0.f;
    for (int i = threadIdx.x; i < n; i += blockDim.x) {
        float v = join2(x[base + i], x[base + i + ps]); ss += v * v;
    }
    ss = blockReduce(ss, false);
    float rn = rsqrtf(ss / (float)n + EPSF);
    for (int i = threadIdx.x; i < n; i += blockDim.x) {
        float v = join2(x[base + i], x[base + i + ps]) * rn * w[i];
        bf16 h, l; split2(v, h, l);
        x[base + i] = h; x[base + i + ps] = l;
    }
}

__global__ void kv_process_k(const bf16* __restrict__ kv, bf16* __restrict__ kext,
                             const float* __restrict__ w, const float* __restrict__ freqs) {
    const long long psKV = (long long)MS * KVD;
    const int m = blockIdx.x;
    const int s = m & (SEQ - 1);
    const bf16* kr = kv   + (long long)m * KVD;
    bf16*       ke = kext + (long long)m * KVD;
    float ss = 0.f;
    for (int i = threadIdx.x; i < KVLR; i += blockDim.x) {
        float v = join2(kr[i], kr[i + psKV]); ss += v * v;
    }
    ss = blockReduce(ss, false);
    float rn = rsqrtf(ss / (float)KVLR + EPSF);
    for (int i = threadIdx.x; i < KVLR; i += blockDim.x) {
        float v = join2(kr[i], kr[i + psKV]) * rn * w[i];
        bf16 h, l; split2(v, h, l);
        ke[i] = h; ke[i + psKV] = l;
    }
    if (threadIdx.x < 32) {
        const int i = threadIdx.x;
        float th = freqs[s * 32 + i];
        float co, sn; sincosf(th, &sn, &co);
        float x0 = join2(kr[KVLR + 2 * i], kr[KVLR + 2 * i + psKV]);
        float x1 = join2(kr[KVLR + 2 * i + 1], kr[KVLR + 2 * i + 1 + psKV]);
        bf16 h, l;
        split2(x0 * co - x1 * sn, h, l);
        ke[KVLR + 2 * i] = h; ke[KVLR + 2 * i + psKV] = l;
        split2(x0 * sn + x1 * co, h, l);
        ke[KVLR + 2 * i + 1] = h; ke[KVLR + 2 * i + 1 + psKV] = l;
    }
}

// rope q_pe in place inside g_q planes ([m][h*192+128 .. +191])
__global__ void rope_q_k(bf16* q, const float* __restrict__ freqs) {
    const long long psQ = (long long)MS * QDIM;
    const int m = blockIdx.x;
    const int s = m & (SEQ - 1);
    const int h = threadIdx.x >> 5;
    const int i = threadIdx.x & 31;
    float th = freqs[s * 32 + i];
    float co, sn; sincosf(th, &sn, &co);
    bf16* qr = q + (long long)m * QDIM + h * D_QK + D_NOPE;
    float x0 = join2(qr[2 * i], qr[2 * i + psQ]);
    float x1 = join2(qr[2 * i + 1], qr[2 * i + 1 + psQ]);
    bf16 hh, ll;
    split2(x0 * co - x1 * sn, hh, ll);
    qr[2 * i] = hh; qr[2 * i + psQ] = ll;
    split2(x0 * sn + x1 * co, hh, ll);
    qr[2 * i + 1] = hh; qr[2 * i + 1 + psQ] = ll;
}

// broadcast roped k_pe into kfull[b,h,s,128:192] for all heads
__global__ void pe_bcast_k(const bf16* __restrict__ kext, bf16* __restrict__ kfull) {
    const long long psKV = (long long)MS * KVD;
    const long long psKF = (long long)BSZ * NH * SEQ * D_QK;
    const int m = blockIdx.x;
    const int s = m & (SEQ - 1);
    const int b = m >> 11;
    const bf16* pe = kext + (long long)m * KVD + KVLR;
    for (int idx = threadIdx.x; idx < NH * D_ROPE; idx += blockDim.x) {
        const int h = idx >> 6, j = idx & 63;
        long long o = (((long long)b * NH + h) * SEQ + s) * D_QK + D_NOPE + j;
        kfull[o] = pe[j];
        kfull[o + psKF] = pe[j + psKV];
    }
}

// ------------------------------- host side ---------------------------------
static void launchGemm(const bf16* A, long long aPS, const bf16* B, long long bPS,
                       void* C, long long cPS,
                       int M, int N, int K,
                       long long lda, long long ldb, long long ldc,
                       int nb, int nInner,
                       long long aSb, long long aSh,
                       long long bSb, long long bSh,
                       long long cSb, long long cSh,
                       int causal, int outMode) {
    GemmP p;
    p.A = A; p.B = B; p.C = C;
    p.aPS = aPS; p.bPS = bPS; p.cPS = cPS;
    p.M = M; p.N = N; p.K = K;
    p.lda = lda; p.ldb = ldb; p.ldc = ldc;
    p.aSb = aSb; p.aSh = aSh; p.bSb = bSb; p.bSh = bSh; p.cSb = cSb; p.cSh = cSh;
    p.nInner = nInner; p.causal = causal; p.outMode = outMode;
    dim3 grid((N + 127) / 128, (M + 127) / 128, nb);
    gemm_hmma<<<grid, 256>>>(p);
}

extern "C" void kernel_launch(void* const* d_in, const int* in_sizes, int n_in,
                              void* d_out, int out_size) {
    const float* x         = (const float*)d_in[0];
    const float* freqs     = (const float*)d_in[1];
    const float* wq_a      = (const float*)d_in[3];
    const float* q_norm_w  = (const float*)d_in[4];
    const float* wq_b      = (const float*)d_in[5];
    const float* wkv_a     = (const float*)d_in[6];
    const float* kv_norm_w = (const float*)d_in[7];
    const float* wkv_b     = (const float*)d_in[8];
    const float* wo        = (const float*)d_in[9];
    float* out = (float*)d_out;

    cudaFuncSetAttribute(flash_k, cudaFuncAttributeMaxDynamicSharedMemorySize, FL_SMEM);

    bf16 *xp, *wqaT, *wkvaT, *wqbT, *wkvbT, *woT;
    bf16 *qa, *q, *kv, *kext, *kfull, *vT, *ohead;
    cudaGetSymbolAddress((void**)&xp,     g_xp);
    cudaGetSymbolAddress((void**)&wqaT,   g_wqaT);
    cudaGetSymbolAddress((void**)&wkvaT,  g_wkvaT);
    cudaGetSymbolAddress((void**)&wqbT,   g_wqbT);
    cudaGetSymbolAddress((void**)&wkvbT,  g_wkvbT);
    cudaGetSymbolAddress((void**)&woT,    g_woT);
    cudaGetSymbolAddress((void**)&qa,     g_qa);
    cudaGetSymbolAddress((void**)&q,      g_q);
    cudaGetSymbolAddress((void**)&kv,     g_kv);
    cudaGetSymbolAddress((void**)&kext,   g_kext);
    cudaGetSymbolAddress((void**)&kfull,  g_kfull);
    cudaGetSymbolAddress((void**)&vT,     g_vT);
    cudaGetSymbolAddress((void**)&ohead,  g_ohead);

    const float scale = 1.0f / sqrtf((float)D_QK);
    const float s2 = scale * 1.4426950408889634f;   // scale * log2(e)

    // plane strides
    const long long psX   = (long long)MS * DMODEL;
    const long long psWQA = (long long)QLR * DMODEL;
    const long long psWKA = (long long)KVD * DMODEL;
    const long long psWQB = (long long)QDIM * QLR;
    const long long psWBT = (long long)NH * HDIM * KVLR;
    const long long psWO  = (long long)DMODEL * DMODEL;
    const long long psQA  = (long long)MS * QLR;
    const long long psQ   = (long long)MS * QDIM;
    const long long psKV  = (long long)MS * KVD;
    const long long psKF  = (long long)BSZ * NH * SEQ * D_QK;
    const long long psVT  = (long long)BSZ * NH * D_V * SEQ;
    const long long psOH  = (long long)MS * DMODEL;

    // ---- pack inputs into planes ----
    pack2_k<<<512, 256>>>(x, xp, psX, MS * DMODEL);
    packT2_k<<<dim3(QLR / 32, DMODEL / 32), dim3(32, 8)>>>(wq_a, wqaT, psWQA, DMODEL, QLR);
    packT2_k<<<dim3(KVD / 32, DMODEL / 32), dim3(32, 8)>>>(wkv_a, wkvaT, psWKA, DMODEL, KVD);
    packT2_k<<<dim3(QDIM / 32, QLR / 32), dim3(32, 8)>>>(wq_b, wqbT, psWQB, QLR, QDIM);
    packT2_k<<<dim3((NH * HDIM) / 32, KVLR / 32), dim3(32, 8)>>>(wkv_b, wkvbT, psWBT, KVLR, NH * HDIM);
    packT2_k<<<dim3(DMODEL / 32, DMODEL / 32), dim3(32, 8)>>>(wo, woT, psWO, DMODEL, DMODEL);

    // 1. qa = x @ wq_a
    launchGemm(xp, psX, wqaT, psWQA, qa, psQA, MS, QLR, DMODEL,
               DMODEL, DMODEL, QLR, 1, 1, 0, 0, 0, 0, 0, 0, 0, 1);
    // 2. kv = x @ wkv_a (N=576)
    launchGemm(xp, psX, wkvaT, psWKA, kv, psKV, MS, KVD, DMODEL,
               DMODEL, DMODEL, KVD, 1, 1, 0, 0, 0, 0, 0, 0, 0, 1);
    // 3. rmsnorm(qa)
    rmsnorm_rows_k<<<MS, 256>>>(qa, psQA, q_norm_w, QLR);
    // 4. kext = [rmsnorm(latent), rope(k_pe)]
    kv_process_k<<<MS, 256>>>(kv, kext, kv_norm_w, freqs);
    // 5. q = qa @ wq_b
    launchGemm(qa, psQA, wqbT, psWQB, q, psQ, MS, QDIM, QLR,
               QLR, QLR, QDIM, 1, 1, 0, 0, 0, 0, 0, 0, 0, 1);
    // 6. rope q_pe in place
    rope_q_k<<<MS, NH * 32>>>(q, freqs);
    // 7. k_abs: kfull[b,h,s,0:128] = kv_cache @ Wuk[h]^T
    launchGemm(kext, psKV, wkvbT, psWBT, kfull, psKF,
               SEQ, D_NOPE, KVLR,
               KVD, KVLR, D_QK,
               BSZ * NH, NH,
               (long long)SEQ * KVD, 0,
               0, (long long)HDIM * KVLR,
               (long long)NH * SEQ * D_QK, (long long)SEQ * D_QK,
               0, 1);
    // 8. broadcast roped k_pe into kfull[...,128:192]
    pe_bcast_k<<<MS, 256>>>(kext, kfull);
    // 9. vT[b,h,d,t] = Wuv[h] @ kv_cache^T
    launchGemm(wkvbT + (long long)D_NOPE * KVLR, psWBT, kext, psKV, vT, psVT,
               D_V, SEQ, KVLR,
               KVLR, KVD, SEQ,
               BSZ * NH, NH,
               0, (long long)HDIM * KVLR,
               (long long)SEQ * KVD, 0,
               (long long)NH * D_V * SEQ, (long long)D_V * SEQ,
               0, 1);
    // 10. fused flash attention -> ohead planes
    flash_k<<<dim3(16, BSZ * NH), 256, FL_SMEM>>>(q, kfull, vT, ohead, s2);
    // 11. out = ohead @ wo (fp32)
    launchGemm(ohead, psOH, woT, psWO, out, 0, MS, DMODEL, DMODEL,
               DMODEL, DMODEL, DMODEL, 1, 1, 0, 0, 0, 0, 0, 0, 0, 0);
}